// round 8
// baseline (speedup 1.0000x reference)
#include <cuda_runtime.h>
#include <cuda_bf16.h>
#include <math.h>
#include <stdint.h>

#define BB 256
#define SS 512
#define HH 1024
#define WW 64
#define MROWS (BB*WW)        // 16384 score rows
#define AROWS (MROWS + BB)   // + 256 hc rows
#define NT 8                 // N tiles of 128
#define BM 128
#define BN 128
#define BK 32                // bf16 K per stage (per plane)
#define KITERS (HH/BK)       // 32
// plane-interleaved rows: [plane0 32bf16 | plane1 32bf16] = 128B, SW128 swizzle
#define B_OFF (BM*128)                 // 16384
#define STAGE_BYTES (2*BM*128)         // 32768 (A tile + B tile)
#define NSTAGE 3
#define SMEM_ALLOC (NSTAGE*STAGE_BYTES) // 98304

// ---------------- scratch ----------------
__device__ __nv_bfloat16 g_A0[(size_t)AROWS*HH];
__device__ __nv_bfloat16 g_A1[(size_t)AROWS*HH];
__device__ __nv_bfloat16 g_W0[(size_t)HH*2*HH];
__device__ __nv_bfloat16 g_W1[(size_t)HH*2*HH];
__device__ float g_u[(size_t)BB*HH];
__device__ float g_part[NT*MROWS];

// ---------------- PTX helpers (no sm_103a-gated features) ----------------
__device__ __forceinline__ uint32_t smem_u32(const void* p) {
    uint32_t a;
    asm("{ .reg .u64 t; cvta.to.shared.u64 t, %1; cvt.u32.u64 %0, t; }" : "=r"(a) : "l"(p));
    return a;
}
__device__ __forceinline__ void cpasync16(uint32_t dst, const void* src) {
    asm volatile("cp.async.cg.shared.global [%0], [%1], 16;" :: "r"(dst), "l"(src) : "memory");
}
__device__ __forceinline__ void cp_commit() { asm volatile("cp.async.commit_group;" ::: "memory"); }
template <int N> __device__ __forceinline__ void cp_wait() {
    asm volatile("cp.async.wait_group %0;" :: "n"(N) : "memory");
}
#define LDSM4(r, addr) \
    asm volatile("ldmatrix.sync.aligned.m8n8.x4.shared.b16 {%0,%1,%2,%3}, [%4];" \
        : "=r"((r)[0]),"=r"((r)[1]),"=r"((r)[2]),"=r"((r)[3]) : "r"(addr))
#define MMA(d, a, b0, b1) \
    asm volatile("mma.sync.aligned.m16n8k16.row.col.f32.bf16.bf16.f32 " \
        "{%0,%1,%2,%3},{%4,%5,%6,%7},{%8,%9},{%0,%1,%2,%3};" \
        : "+f"((d)[0]),"+f"((d)[1]),"+f"((d)[2]),"+f"((d)[3]) \
        : "r"((a)[0]),"r"((a)[1]),"r"((a)[2]),"r"((a)[3]),"r"(b0),"r"(b1))

// ---------------- split helpers ----------------
__device__ __forceinline__ void split2(float x, __nv_bfloat16& a0, __nv_bfloat16& a1) {
    a0 = __float2bfloat16_rn(x);
    a1 = __float2bfloat16_rn(x - __bfloat162float(a0));
}

// ---------------- kernel: split W into 2 bf16 planes ----------------
__global__ __launch_bounds__(256) void split_w(const float* __restrict__ Wa) {
    size_t base = ((size_t)blockIdx.x * 256 + threadIdx.x) * 4;
    float4 x = *reinterpret_cast<const float4*>(Wa + base);
    float v4[4] = {x.x, x.y, x.z, x.w};
    __nv_bfloat16 s0[4], s1[4];
    #pragma unroll
    for (int i = 0; i < 4; i++) split2(v4[i], s0[i], s1[i]);
    #pragma unroll
    for (int i = 0; i < 2; i++) {
        reinterpret_cast<__nv_bfloat162*>(g_W0 + base)[i] = __nv_bfloat162(s0[2*i], s0[2*i+1]);
        reinterpret_cast<__nv_bfloat162*>(g_W1 + base)[i] = __nv_bfloat162(s1[2*i], s1[2*i+1]);
    }
}

// ---------------- kernel: gather rows + split ----------------
__global__ __launch_bounds__(256) void gather_split_a(const float* __restrict__ inp,
                                                      const float* __restrict__ hc,
                                                      const int* __restrict__ slen) {
    int row = blockIdx.x;
    const float* src;
    if (row < MROWS) {
        int b = row >> 6, w = row & 63;
        src = inp + ((size_t)b * SS + (slen[b] - WW + w)) * HH;
    } else {
        src = hc + (size_t)(row - MROWS) * HH;
    }
    int i = threadIdx.x * 4;
    float4 x = *reinterpret_cast<const float4*>(src + i);
    float v4[4] = {x.x, x.y, x.z, x.w};
    __nv_bfloat16 s0[4], s1[4];
    #pragma unroll
    for (int k = 0; k < 4; k++) split2(v4[k], s0[k], s1[k]);
    size_t base = (size_t)row * HH + i;
    #pragma unroll
    for (int k = 0; k < 2; k++) {
        reinterpret_cast<__nv_bfloat162*>(g_A0 + base)[k] = __nv_bfloat162(s0[2*k], s0[2*k+1]);
        reinterpret_cast<__nv_bfloat162*>(g_A1 + base)[k] = __nv_bfloat162(s1[2*k], s1[2*k+1]);
    }
}

// ---------------- HMMA GEMM: emulated fp32 via 3 bf16 products ----------------
// (a0+a1)(b0+b1) ~= a0b0 + a0b1 + a1b0  (a1b1 ~ 2^-18 rel, dropped)
// 3-stage cp.async pipeline; A fragments for both ks preloaded; B ldmatrix
// stream double-buffered one unit ahead of its MMAs.
__global__ __launch_bounds__(256, 2) void gemm_hmma(int mode, int arow_base, int kofs,
                                                    const float* __restrict__ vv,
                                                    const float* __restrict__ ba) {
    extern __shared__ __align__(1024) char smem_raw[];
    const uint32_t sbase = smem_u32(smem_raw);
    __shared__ float srow[2][BM];

    const int tid = threadIdx.x;
    const int lane = tid & 31;
    const int wid = tid >> 5;
    const int wm = (wid & 3) * 32;     // warp M offset
    const int wn = (wid >> 2) * 64;    // warp N offset
    const int n0 = blockIdx.x * BN;    // x = n-tile (A reuse in L2)
    const int m0 = blockIdx.y * BM;

    // ---- fill: per-thread p/kc/swizzle are j-invariant -> 2 bases + strides ----
    const int fp = (tid >> 2) & 1;     // plane
    const int fkc = tid & 3;           // 16B chunk within 32-elt half-row
    const int fr0 = tid >> 3;          // first row (rows fr0 + j*32)
    const __nv_bfloat16* fbaseA = (fp ? g_A1 : g_A0)
        + (size_t)(arow_base + m0 + fr0) * HH + fkc * 8;
    const __nv_bfloat16* fbaseB = (fp ? g_W1 : g_W0)
        + (size_t)(n0 + fr0) * (2 * HH) + kofs + fkc * 8;
    const uint32_t fdstA = fr0 * 128 + (((tid & 7) * 16) ^ ((fr0 & 7) << 4));
    const uint32_t fdstB = B_OFF + fdstA;

    auto fill = [&](int s, int k0) {
        uint32_t stg = sbase + s * STAGE_BYTES;
        #pragma unroll
        for (int j = 0; j < 4; j++)
            cpasync16(stg + fdstA + j * 4096, fbaseA + (size_t)j * 32 * HH + k0);
        #pragma unroll
        for (int j = 0; j < 4; j++)
            cpasync16(stg + fdstB + j * 4096, fbaseB + (size_t)j * 64 * HH + k0);
    };

    float acc[2][8][4] = {};
    // ---- LDSM bases + swizzled column constants ----
    const uint32_t lrow = lane & 15;
    const uint32_t hi16 = (lane >> 4) * 16;
    const uint32_t swm = (lrow & 7) << 4;
    uint32_t csw[2][2];   // csw[p][ks]
    #pragma unroll
    for (int p = 0; p < 2; p++)
        #pragma unroll
        for (int ks = 0; ks < 2; ks++)
            csw[p][ks] = ((uint32_t)(p * 64 + ks * 32) + hi16) ^ swm;
    const uint32_t aBase = sbase + (wm + lrow) * 128;
    const uint32_t bBase = sbase + B_OFF + (wn + lrow) * 128;

    fill(0, 0);
    cp_commit();
    fill(1, BK);
    cp_commit();

    uint32_t soff = 0;
    for (int it = 0; it < KITERS; ++it) {
        if (it + 1 < KITERS) cp_wait<1>(); else cp_wait<0>();
        __syncthreads();                     // publish fill(it); stage (it+2)%3 free
        if (it + 2 < KITERS) {
            fill((it + 2) % NSTAGE, (it + 2) * BK);
            cp_commit();
        }

        const uint32_t aAddr = aBase + soff;
        const uint32_t bAddr = bBase + soff;

        // preload A fragments for BOTH ks halves (8 LDSMs, 32 regs)
        uint32_t a0f[2][2][4], a1f[2][2][4];    // [ks][mi][4]
        #pragma unroll
        for (int ks = 0; ks < 2; ks++)
            #pragma unroll
            for (int mi = 0; mi < 2; mi++) {
                LDSM4(a0f[ks][mi], aAddr + mi * 2048 + csw[0][ks]);
                LDSM4(a1f[ks][mi], aAddr + mi * 2048 + csw[1][ks]);
            }

        // B stream: 16 units u = ks*8 + n2*2 + p, double-buffered one ahead
        uint32_t bq[2][4];
        LDSM4(bq[0], bAddr + csw[0][0]);     // unit 0: ks0,n2=0,p0
        #pragma unroll
        for (int u = 0; u < 16; u++) {
            const int ks = u >> 3, n2 = (u >> 1) & 3, pp = u & 1;
            if (u + 1 < 16) {
                const int v = u + 1;
                LDSM4(bq[v & 1], bAddr + (((v >> 1) & 3) * 2048) + csw[v & 1][v >> 3]);
            }
            const uint32_t* bc = bq[u & 1];
            #pragma unroll
            for (int mi = 0; mi < 2; mi++) {
                MMA(acc[mi][2*n2],   a0f[ks][mi], bc[0], bc[2]);
                MMA(acc[mi][2*n2+1], a0f[ks][mi], bc[1], bc[3]);
            }
            if (pp == 0) {
                #pragma unroll
                for (int mi = 0; mi < 2; mi++) {
                    MMA(acc[mi][2*n2],   a1f[ks][mi], bc[0], bc[2]);
                    MMA(acc[mi][2*n2+1], a1f[ks][mi], bc[1], bc[3]);
                }
            }
        }
        soff = (soff == (NSTAGE - 1) * STAGE_BYTES) ? 0 : soff + STAGE_BYTES;
    }

    const int quad = lane >> 2, qt = lane & 3;

    if (mode == 1) {
        // epilogue: s_row = sum_n v[n]*tanh(E + u[b,n]); per-warp rows all in one batch
        const int b_warp = (m0 + wm) >> 6;
        const float* up = g_u + (size_t)b_warp * HH + n0 + wn;
        const float* vp = vv + n0 + wn;
        float rs[4] = {0.f, 0.f, 0.f, 0.f};
        #pragma unroll
        for (int mi = 0; mi < 2; mi++)
            #pragma unroll
            for (int ni = 0; ni < 8; ni++)
                #pragma unroll
                for (int r = 0; r < 4; r++) {
                    int col = ni * 8 + qt * 2 + (r & 1);
                    float e = acc[mi][ni][r] + __ldg(up + col);
                    rs[mi * 2 + (r >> 1)] += __ldg(vp + col) * tanhf(e);
                }
        #pragma unroll
        for (int i = 0; i < 4; i++) {
            rs[i] += __shfl_xor_sync(0xffffffffu, rs[i], 1);
            rs[i] += __shfl_xor_sync(0xffffffffu, rs[i], 2);
        }
        __syncthreads();
        if (qt == 0) {
            #pragma unroll
            for (int mi = 0; mi < 2; mi++)
                #pragma unroll
                for (int hf = 0; hf < 2; hf++)
                    srow[wid >> 2][wm + mi * 16 + hf * 8 + quad] = rs[mi * 2 + hf];
        }
        __syncthreads();
        if (tid < BM)
            g_part[blockIdx.x * MROWS + m0 + tid] = srow[0][tid] + srow[1][tid];
    } else {
        // u = D + b_attn
        #pragma unroll
        for (int mi = 0; mi < 2; mi++)
            #pragma unroll
            for (int ni = 0; ni < 8; ni++)
                #pragma unroll
                for (int r = 0; r < 4; r++) {
                    int row = m0 + wm + mi * 16 + (r >> 1) * 8 + quad;
                    int col = n0 + wn + ni * 8 + qt * 2 + (r & 1);
                    g_u[(size_t)row * HH + col] = acc[mi][ni][r] + __ldg(ba + col);
                }
    }
}

// ---------------- finalize: softmax + context + parent ----------------
// grid (BB, 4): block y covers 256 h-columns
__global__ __launch_bounds__(256) void finalize(const float* __restrict__ inp,
                                                const int* __restrict__ slen,
                                                const int* __restrict__ parent,
                                                float* __restrict__ out) {
    const int b = blockIdx.x;
    const int h0 = blockIdx.y * 256;
    const int tid = threadIdx.x;
    __shared__ float ssc[WW];
    __shared__ float sattn[WW];
    const int len = slen[b];

    if (tid < WW) {
        float s = 0.f;
        #pragma unroll
        for (int t = 0; t < NT; t++) s += g_part[t * MROWS + b * WW + tid];
        ssc[tid] = s;
    }
    __syncthreads();

    float mx = -1e30f;
    #pragma unroll 8
    for (int w = 0; w < WW; w++) mx = fmaxf(mx, ssc[w]);
    float sum = 0.f;
    #pragma unroll 8
    for (int w = 0; w < WW; w++) sum += expf(ssc[w] - mx);
    float inv = 1.f / sum;

    if (tid < WW) {
        float a = expf(ssc[tid] - mx) * inv;
        if (blockIdx.y == 0) out[b * WW + tid] = a;
        sattn[tid] = a;
    }
    __syncthreads();

    const float* base = inp + (size_t)b * SS * HH;
    const int off0 = (len - WW) * HH;
    {
        int h = h0 + tid;
        float acc = 0.f;
        #pragma unroll 8
        for (int w = 0; w < WW; w++)
            acc = fmaf(sattn[w], base[off0 + w * HH + h], acc);
        out[MROWS + b * HH + h] = acc;
        const int poff = (len - parent[b] - 1) * HH;
        out[MROWS + BB * HH + b * HH + h] = base[poff + h];
    }
}

// ---------------------------------------------------------------------------
extern "C" void kernel_launch(void* const* d_in, const int* in_sizes, int n_in,
                              void* d_out, int out_size) {
    const float* inp    = (const float*)d_in[0];
    const float* hc     = (const float*)d_in[1];
    const float* Wa     = (const float*)d_in[2];
    const float* ba     = (const float*)d_in[3];
    const float* v      = (const float*)d_in[4];
    const int*   slen   = (const int*)d_in[5];
    const int*   parent = (const int*)d_in[6];
    float* out = (float*)d_out;

    static int configured = 0;
    if (!configured) {
        cudaFuncSetAttribute(gemm_hmma, cudaFuncAttributeMaxDynamicSharedMemorySize, SMEM_ALLOC);
        configured = 1;
    }

    split_w<<<(HH * 2 * HH) / 1024, 256>>>(Wa);
    gather_split_a<<<AROWS, 256>>>(inp, hc, slen);
    gemm_hmma<<<dim3(NT, BB / BM), 256, SMEM_ALLOC>>>(0, MROWS, 0, v, ba);   // u
    gemm_hmma<<<dim3(NT, MROWS / BM), 256, SMEM_ALLOC>>>(1, 0, HH, v, ba);   // scores
    finalize<<<dim3(BB, 4), 256>>>(inp, slen, parent, out);
}

// round 9
// speedup vs baseline: 1.5049x; 1.5049x over previous
#include <cuda_runtime.h>
#include <cuda_bf16.h>
#include <math.h>
#include <stdint.h>

#define BB 256
#define SS 512
#define HH 1024
#define WW 64
#define MROWS (BB*WW)        // 16384 score rows
#define AROWS (MROWS + BB)   // + 256 hc rows
#define NT 8                 // N tiles of 128
#define BM 128
#define BN 128
#define BK 32                // bf16 K per stage (per plane)
#define KITERS (HH/BK)       // 32
// plane-interleaved rows: [plane0 32bf16 | plane1 32bf16] = 128B, SW128 swizzle
#define B_OFF (BM*128)                 // 16384
#define STAGE_BYTES (2*BM*128)         // 32768 (A tile + B tile)
#define NSTAGE 3
#define SMEM_ALLOC (NSTAGE*STAGE_BYTES) // 98304

// ---------------- scratch ----------------
__device__ __nv_bfloat16 g_A0[(size_t)AROWS*HH];
__device__ __nv_bfloat16 g_A1[(size_t)AROWS*HH];
__device__ __nv_bfloat16 g_W0[(size_t)HH*2*HH];
__device__ __nv_bfloat16 g_W1[(size_t)HH*2*HH];
__device__ float g_u[(size_t)BB*HH];
__device__ float g_part[NT*MROWS];

// ---------------- PTX helpers (no sm_103a-gated features) ----------------
__device__ __forceinline__ uint32_t smem_u32(const void* p) {
    uint32_t a;
    asm("{ .reg .u64 t; cvta.to.shared.u64 t, %1; cvt.u32.u64 %0, t; }" : "=r"(a) : "l"(p));
    return a;
}
__device__ __forceinline__ void cpasync16(uint32_t dst, const void* src) {
    asm volatile("cp.async.cg.shared.global [%0], [%1], 16;" :: "r"(dst), "l"(src) : "memory");
}
__device__ __forceinline__ void cp_commit() { asm volatile("cp.async.commit_group;" ::: "memory"); }
template <int N> __device__ __forceinline__ void cp_wait() {
    asm volatile("cp.async.wait_group %0;" :: "n"(N) : "memory");
}
#define LDSM4(r, addr) \
    asm volatile("ldmatrix.sync.aligned.m8n8.x4.shared.b16 {%0,%1,%2,%3}, [%4];" \
        : "=r"((r)[0]),"=r"((r)[1]),"=r"((r)[2]),"=r"((r)[3]) : "r"(addr))
#define MMA(d, a, b0, b1) \
    asm volatile("mma.sync.aligned.m16n8k16.row.col.f32.bf16.bf16.f32 " \
        "{%0,%1,%2,%3},{%4,%5,%6,%7},{%8,%9},{%0,%1,%2,%3};" \
        : "+f"((d)[0]),"+f"((d)[1]),"+f"((d)[2]),"+f"((d)[3]) \
        : "r"((a)[0]),"r"((a)[1]),"r"((a)[2]),"r"((a)[3]),"r"(b0),"r"(b1))

// ---------------- split helpers ----------------
__device__ __forceinline__ void split2(float x, __nv_bfloat16& a0, __nv_bfloat16& a1) {
    a0 = __float2bfloat16_rn(x);
    a1 = __float2bfloat16_rn(x - __bfloat162float(a0));
}

// ---------------- kernel: split W into 2 bf16 planes ----------------
__global__ __launch_bounds__(256) void split_w(const float* __restrict__ Wa) {
    size_t base = ((size_t)blockIdx.x * 256 + threadIdx.x) * 4;
    float4 x = *reinterpret_cast<const float4*>(Wa + base);
    float v4[4] = {x.x, x.y, x.z, x.w};
    __nv_bfloat16 s0[4], s1[4];
    #pragma unroll
    for (int i = 0; i < 4; i++) split2(v4[i], s0[i], s1[i]);
    #pragma unroll
    for (int i = 0; i < 2; i++) {
        reinterpret_cast<__nv_bfloat162*>(g_W0 + base)[i] = __nv_bfloat162(s0[2*i], s0[2*i+1]);
        reinterpret_cast<__nv_bfloat162*>(g_W1 + base)[i] = __nv_bfloat162(s1[2*i], s1[2*i+1]);
    }
}

// ---------------- kernel: gather rows + split ----------------
__global__ __launch_bounds__(256) void gather_split_a(const float* __restrict__ inp,
                                                      const float* __restrict__ hc,
                                                      const int* __restrict__ slen) {
    int row = blockIdx.x;
    const float* src;
    if (row < MROWS) {
        int b = row >> 6, w = row & 63;
        src = inp + ((size_t)b * SS + (slen[b] - WW + w)) * HH;
    } else {
        src = hc + (size_t)(row - MROWS) * HH;
    }
    int i = threadIdx.x * 4;
    float4 x = *reinterpret_cast<const float4*>(src + i);
    float v4[4] = {x.x, x.y, x.z, x.w};
    __nv_bfloat16 s0[4], s1[4];
    #pragma unroll
    for (int k = 0; k < 4; k++) split2(v4[k], s0[k], s1[k]);
    size_t base = (size_t)row * HH + i;
    #pragma unroll
    for (int k = 0; k < 2; k++) {
        reinterpret_cast<__nv_bfloat162*>(g_A0 + base)[k] = __nv_bfloat162(s0[2*k], s0[2*k+1]);
        reinterpret_cast<__nv_bfloat162*>(g_A1 + base)[k] = __nv_bfloat162(s1[2*k], s1[2*k+1]);
    }
}

// ---------------- HMMA GEMM: emulated fp32 via 3 bf16 products ----------------
// (a0+a1)(b0+b1) ~= a0b0 + a0b1 + a1b0  (a1b1 ~ 2^-18 rel, dropped)
// 3-stage cp.async pipeline; A fragments per-ks (16 regs); B ldmatrix stream
// double-buffered one unit ahead (bq = +4 regs only).
__global__ __launch_bounds__(256, 2) void gemm_hmma(int mode, int arow_base, int kofs,
                                                    const float* __restrict__ vv,
                                                    const float* __restrict__ ba) {
    extern __shared__ __align__(1024) char smem_raw[];
    const uint32_t sbase = smem_u32(smem_raw);
    __shared__ float srow[2][BM];

    const int tid = threadIdx.x;
    const int lane = tid & 31;
    const int wid = tid >> 5;
    const int wm = (wid & 3) * 32;     // warp M offset
    const int wn = (wid >> 2) * 64;    // warp N offset
    const int n0 = blockIdx.x * BN;    // x = n-tile (A reuse in L2)
    const int m0 = blockIdx.y * BM;

    // ---- fill: per-thread p/kc/swizzle are j-invariant -> 2 bases + strides ----
    const int fp = (tid >> 2) & 1;     // plane
    const int fkc = tid & 3;           // 16B chunk within 32-elt half-row
    const int fr0 = tid >> 3;          // first row (rows fr0 + j*32)
    const __nv_bfloat16* fbaseA = (fp ? g_A1 : g_A0)
        + (size_t)(arow_base + m0 + fr0) * HH + fkc * 8;
    const __nv_bfloat16* fbaseB = (fp ? g_W1 : g_W0)
        + (size_t)(n0 + fr0) * (2 * HH) + kofs + fkc * 8;
    const uint32_t fdstA = fr0 * 128 + (((tid & 7) * 16) ^ ((fr0 & 7) << 4));
    const uint32_t fdstB = B_OFF + fdstA;

    auto fill = [&](int s, int k0) {
        uint32_t stg = sbase + s * STAGE_BYTES;
        #pragma unroll
        for (int j = 0; j < 4; j++)
            cpasync16(stg + fdstA + j * 4096, fbaseA + (size_t)j * 32 * HH + k0);
        #pragma unroll
        for (int j = 0; j < 4; j++)
            cpasync16(stg + fdstB + j * 4096, fbaseB + (size_t)j * 64 * HH + k0);
    };

    float acc[2][8][4] = {};
    // ---- LDSM bases + swizzled column constants ----
    const uint32_t lrow = lane & 15;
    const uint32_t hi16 = (lane >> 4) * 16;
    const uint32_t swm = (lrow & 7) << 4;
    uint32_t csw[2][2];   // csw[p][ks]
    #pragma unroll
    for (int p = 0; p < 2; p++)
        #pragma unroll
        for (int ks = 0; ks < 2; ks++)
            csw[p][ks] = ((uint32_t)(p * 64 + ks * 32) + hi16) ^ swm;
    const uint32_t aBase = sbase + (wm + lrow) * 128;
    const uint32_t bBase = sbase + B_OFF + (wn + lrow) * 128;

    fill(0, 0);
    cp_commit();
    fill(1, BK);
    cp_commit();

    uint32_t soff = 0;
    for (int it = 0; it < KITERS; ++it) {
        if (it + 1 < KITERS) cp_wait<1>(); else cp_wait<0>();
        __syncthreads();                     // publish fill(it); stage (it+2)%3 free
        if (it + 2 < KITERS) {
            fill((it + 2) % NSTAGE, (it + 2) * BK);
            cp_commit();
        }

        const uint32_t aAddr = aBase + soff;
        const uint32_t bAddr = bBase + soff;

        uint32_t a0f[2][4], a1f[2][4];       // current-ks A fragments
        uint32_t bq[2][4];                   // B double buffer
        LDSM4(bq[0], bAddr + csw[0][0]);     // unit 0: ks0,n2=0,p0

        // 16 B-units: u = ks*8 + n2*2 + p
        #pragma unroll
        for (int u = 0; u < 16; u++) {
            const int ks = u >> 3, n2 = (u >> 1) & 3, pp = u & 1;
            if ((u & 7) == 0) {              // (re)load A for this ks half
                #pragma unroll
                for (int mi = 0; mi < 2; mi++) {
                    LDSM4(a0f[mi], aAddr + mi * 2048 + csw[0][ks]);
                    LDSM4(a1f[mi], aAddr + mi * 2048 + csw[1][ks]);
                }
            }
            if (u + 1 < 16) {
                const int v = u + 1;
                LDSM4(bq[v & 1], bAddr + (((v >> 1) & 3) * 2048) + csw[v & 1][v >> 3]);
            }
            const uint32_t* bc = bq[u & 1];
            #pragma unroll
            for (int mi = 0; mi < 2; mi++) {
                MMA(acc[mi][2*n2],   a0f[mi], bc[0], bc[2]);
                MMA(acc[mi][2*n2+1], a0f[mi], bc[1], bc[3]);
            }
            if (pp == 0) {
                #pragma unroll
                for (int mi = 0; mi < 2; mi++) {
                    MMA(acc[mi][2*n2],   a1f[mi], bc[0], bc[2]);
                    MMA(acc[mi][2*n2+1], a1f[mi], bc[1], bc[3]);
                }
            }
        }
        soff = (soff == (NSTAGE - 1) * STAGE_BYTES) ? 0 : soff + STAGE_BYTES;
    }

    const int quad = lane >> 2, qt = lane & 3;

    if (mode == 1) {
        // epilogue: s_row = sum_n v[n]*tanh(E + u[b,n]); per-warp rows all in one batch
        const int b_warp = (m0 + wm) >> 6;
        const float* up = g_u + (size_t)b_warp * HH + n0 + wn;
        const float* vp = vv + n0 + wn;
        float rs[4] = {0.f, 0.f, 0.f, 0.f};
        #pragma unroll
        for (int mi = 0; mi < 2; mi++)
            #pragma unroll
            for (int ni = 0; ni < 8; ni++)
                #pragma unroll
                for (int r = 0; r < 4; r++) {
                    int col = ni * 8 + qt * 2 + (r & 1);
                    float e = acc[mi][ni][r] + __ldg(up + col);
                    rs[mi * 2 + (r >> 1)] += __ldg(vp + col) * tanhf(e);
                }
        #pragma unroll
        for (int i = 0; i < 4; i++) {
            rs[i] += __shfl_xor_sync(0xffffffffu, rs[i], 1);
            rs[i] += __shfl_xor_sync(0xffffffffu, rs[i], 2);
        }
        __syncthreads();
        if (qt == 0) {
            #pragma unroll
            for (int mi = 0; mi < 2; mi++)
                #pragma unroll
                for (int hf = 0; hf < 2; hf++)
                    srow[wid >> 2][wm + mi * 16 + hf * 8 + quad] = rs[mi * 2 + hf];
        }
        __syncthreads();
        if (tid < BM)
            g_part[blockIdx.x * MROWS + m0 + tid] = srow[0][tid] + srow[1][tid];
    } else {
        // u = D + b_attn
        #pragma unroll
        for (int mi = 0; mi < 2; mi++)
            #pragma unroll
            for (int ni = 0; ni < 8; ni++)
                #pragma unroll
                for (int r = 0; r < 4; r++) {
                    int row = m0 + wm + mi * 16 + (r >> 1) * 8 + quad;
                    int col = n0 + wn + ni * 8 + qt * 2 + (r & 1);
                    g_u[(size_t)row * HH + col] = acc[mi][ni][r] + __ldg(ba + col);
                }
    }
}

// ---------------- finalize: softmax + context + parent ----------------
// grid (BB, 4): block y covers 256 h-columns
__global__ __launch_bounds__(256) void finalize(const float* __restrict__ inp,
                                                const int* __restrict__ slen,
                                                const int* __restrict__ parent,
                                                float* __restrict__ out) {
    const int b = blockIdx.x;
    const int h0 = blockIdx.y * 256;
    const int tid = threadIdx.x;
    __shared__ float ssc[WW];
    __shared__ float sattn[WW];
    const int len = slen[b];

    if (tid < WW) {
        float s = 0.f;
        #pragma unroll
        for (int t = 0; t < NT; t++) s += g_part[t * MROWS + b * WW + tid];
        ssc[tid] = s;
    }
    __syncthreads();

    float mx = -1e30f;
    #pragma unroll 8
    for (int w = 0; w < WW; w++) mx = fmaxf(mx, ssc[w]);
    float sum = 0.f;
    #pragma unroll 8
    for (int w = 0; w < WW; w++) sum += expf(ssc[w] - mx);
    float inv = 1.f / sum;

    if (tid < WW) {
        float a = expf(ssc[tid] - mx) * inv;
        if (blockIdx.y == 0) out[b * WW + tid] = a;
        sattn[tid] = a;
    }
    __syncthreads();

    const float* base = inp + (size_t)b * SS * HH;
    const int off0 = (len - WW) * HH;
    {
        int h = h0 + tid;
        float acc = 0.f;
        #pragma unroll 8
        for (int w = 0; w < WW; w++)
            acc = fmaf(sattn[w], base[off0 + w * HH + h], acc);
        out[MROWS + b * HH + h] = acc;
        const int poff = (len - parent[b] - 1) * HH;
        out[MROWS + BB * HH + b * HH + h] = base[poff + h];
    }
}

// ---------------------------------------------------------------------------
extern "C" void kernel_launch(void* const* d_in, const int* in_sizes, int n_in,
                              void* d_out, int out_size) {
    const float* inp    = (const float*)d_in[0];
    const float* hc     = (const float*)d_in[1];
    const float* Wa     = (const float*)d_in[2];
    const float* ba     = (const float*)d_in[3];
    const float* v      = (const float*)d_in[4];
    const int*   slen   = (const int*)d_in[5];
    const int*   parent = (const int*)d_in[6];
    float* out = (float*)d_out;

    static int configured = 0;
    if (!configured) {
        cudaFuncSetAttribute(gemm_hmma, cudaFuncAttributeMaxDynamicSharedMemorySize, SMEM_ALLOC);
        configured = 1;
    }

    split_w<<<(HH * 2 * HH) / 1024, 256>>>(Wa);
    gather_split_a<<<AROWS, 256>>>(inp, hc, slen);
    gemm_hmma<<<dim3(NT, BB / BM), 256, SMEM_ALLOC>>>(0, MROWS, 0, v, ba);   // u
    gemm_hmma<<<dim3(NT, MROWS / BM), 256, SMEM_ALLOC>>>(1, 0, HH, v, ba);   // scores
    finalize<<<dim3(BB, 4), 256>>>(inp, slen, parent, out);
}

// round 10
// speedup vs baseline: 2.0264x; 1.3465x over previous
#include <cuda_runtime.h>
#include <cuda_fp16.h>
#include <math.h>
#include <stdint.h>

#define BB 256
#define SS 512
#define HH 1024
#define WW 64
#define MROWS (BB*WW)        // 16384 score rows
#define AROWS (MROWS + BB)   // + 256 hc rows
#define NT 8                 // N tiles of 128
#define BM 128
#define BN 128
#define BK 32                // fp16 K per stage
#define KITERS (HH/BK)       // 32
// A rows: [a0 32fp16 | a1 32fp16] = 128B, SW128. B rows: 32 fp16 = 64B,
// two logical rows packed per 128B physical row.
#define B_OFF (BM*128)                 // 16384 (A tile)
#define STAGE_BYTES (B_OFF + (BN/2)*128) // 16384 + 8192 = 24576
#define NSTAGE 4
#define SMEM_ALLOC (NSTAGE*STAGE_BYTES) // 98304

// ---------------- scratch ----------------
__device__ __half g_A0[(size_t)AROWS*HH];
__device__ __half g_A1[(size_t)AROWS*HH];
__device__ __half g_Wh[(size_t)HH*2*HH];
__device__ float g_u[(size_t)BB*HH];
__device__ float g_part[NT*MROWS];

// ---------------- PTX helpers (no sm_103a-gated features) ----------------
__device__ __forceinline__ uint32_t smem_u32(const void* p) {
    uint32_t a;
    asm("{ .reg .u64 t; cvta.to.shared.u64 t, %1; cvt.u32.u64 %0, t; }" : "=r"(a) : "l"(p));
    return a;
}
__device__ __forceinline__ void cpasync16(uint32_t dst, const void* src) {
    asm volatile("cp.async.cg.shared.global [%0], [%1], 16;" :: "r"(dst), "l"(src) : "memory");
}
__device__ __forceinline__ void cp_commit() { asm volatile("cp.async.commit_group;" ::: "memory"); }
template <int N> __device__ __forceinline__ void cp_wait() {
    asm volatile("cp.async.wait_group %0;" :: "n"(N) : "memory");
}
#define LDSM4(r, addr) \
    asm volatile("ldmatrix.sync.aligned.m8n8.x4.shared.b16 {%0,%1,%2,%3}, [%4];" \
        : "=r"((r)[0]),"=r"((r)[1]),"=r"((r)[2]),"=r"((r)[3]) : "r"(addr))
#define MMA(d, a, b0, b1) \
    asm volatile("mma.sync.aligned.m16n8k16.row.col.f32.f16.f16.f32 " \
        "{%0,%1,%2,%3},{%4,%5,%6,%7},{%8,%9},{%0,%1,%2,%3};" \
        : "+f"((d)[0]),"+f"((d)[1]),"+f"((d)[2]),"+f"((d)[3]) \
        : "r"((a)[0]),"r"((a)[1]),"r"((a)[2]),"r"((a)[3]),"r"(b0),"r"(b1))

// ---------------- split helpers ----------------
__device__ __forceinline__ void split2h(float x, __half& a0, __half& a1) {
    a0 = __float2half_rn(x);
    a1 = __float2half_rn(x - __half2float(a0));
}

// ---------------- kernel: convert W to single fp16 plane ----------------
__global__ __launch_bounds__(256) void convert_w(const float* __restrict__ Wa) {
    size_t base = ((size_t)blockIdx.x * 256 + threadIdx.x) * 4;
    float4 x = *reinterpret_cast<const float4*>(Wa + base);
    __half2 h0 = __floats2half2_rn(x.x, x.y);
    __half2 h1 = __floats2half2_rn(x.z, x.w);
    reinterpret_cast<__half2*>(g_Wh + base)[0] = h0;
    reinterpret_cast<__half2*>(g_Wh + base)[1] = h1;
}

// ---------------- kernel: gather rows + 2-way fp16 split ----------------
__global__ __launch_bounds__(256) void gather_split_a(const float* __restrict__ inp,
                                                      const float* __restrict__ hc,
                                                      const int* __restrict__ slen) {
    int row = blockIdx.x;
    const float* src;
    if (row < MROWS) {
        int b = row >> 6, w = row & 63;
        src = inp + ((size_t)b * SS + (slen[b] - WW + w)) * HH;
    } else {
        src = hc + (size_t)(row - MROWS) * HH;
    }
    int i = threadIdx.x * 4;
    float4 x = *reinterpret_cast<const float4*>(src + i);
    float v4[4] = {x.x, x.y, x.z, x.w};
    __half s0[4], s1[4];
    #pragma unroll
    for (int k = 0; k < 4; k++) split2h(v4[k], s0[k], s1[k]);
    size_t base = (size_t)row * HH + i;
    #pragma unroll
    for (int k = 0; k < 2; k++) {
        reinterpret_cast<__half2*>(g_A0 + base)[k] = __halves2half2(s0[2*k], s0[2*k+1]);
        reinterpret_cast<__half2*>(g_A1 + base)[k] = __halves2half2(s1[2*k], s1[2*k+1]);
    }
}

// ---------------- HMMA GEMM: fp32 emulated via 2 fp16 products ----------------
// a = a0 + a1 (fp16 split, residual ~2^-22); b single fp16 (rounding 2^-11,
// statistically cancelling over K). E = A0*B + A1*B.
// 4-stage cp.async pipeline.
__global__ __launch_bounds__(256, 2) void gemm_hmma(int mode, int arow_base, int kofs,
                                                    const float* __restrict__ vv,
                                                    const float* __restrict__ ba) {
    extern __shared__ __align__(1024) char smem_raw[];
    const uint32_t sbase = smem_u32(smem_raw);
    __shared__ float srow[2][BM];

    const int tid = threadIdx.x;
    const int lane = tid & 31;
    const int wid = tid >> 5;
    const int wm = (wid & 3) * 32;     // warp M offset
    const int wn = (wid >> 2) * 64;    // warp N offset
    const int n0 = blockIdx.x * BN;    // x = n-tile (A reuse in L2)
    const int m0 = blockIdx.y * BM;

    // ---- A fill: 4 chunks/thread (rows fr0 + j*32) ----
    const int fp = (tid >> 2) & 1;     // plane
    const int fkc = tid & 3;           // 16B chunk within 32-elt half
    const int fr0 = tid >> 3;
    const __half* fbaseA = (fp ? g_A1 : g_A0)
        + (size_t)(arow_base + m0 + fr0) * HH + fkc * 8;
    const uint32_t fdstA = fr0 * 128 + (((tid & 7) * 16) ^ ((fr0 & 7) << 4));
    // ---- B fill: 2 chunks/thread (rows rb0, rb0+64) ----
    const int rb0 = tid >> 2;          // logical B row for j=0
    const __half* fbaseB0 = g_Wh + (size_t)(n0 + rb0) * (2 * HH) + kofs + fkc * 8;
    const __half* fbaseB1 = g_Wh + (size_t)(n0 + rb0 + 64) * (2 * HH) + kofs + fkc * 8;
    uint32_t fdstB0, fdstB1;
    {
        int q = rb0 >> 1;
        fdstB0 = B_OFF + q * 128 + ((((rb0 & 1) * 64) + fkc * 16) ^ ((q & 7) << 4));
        int r1 = rb0 + 64, q1 = r1 >> 1;
        fdstB1 = B_OFF + q1 * 128 + ((((r1 & 1) * 64) + fkc * 16) ^ ((q1 & 7) << 4));
    }

    auto fill = [&](int s, int k0) {
        uint32_t stg = sbase + s * STAGE_BYTES;
        #pragma unroll
        for (int j = 0; j < 4; j++)
            cpasync16(stg + fdstA + j * 4096, fbaseA + (size_t)j * 32 * HH + k0);
        cpasync16(stg + fdstB0, fbaseB0 + k0);
        cpasync16(stg + fdstB1, fbaseB1 + k0);
    };

    float acc[2][8][4] = {};
    // ---- LDSM bases + swizzled constants ----
    const uint32_t lrow = lane & 15;
    const uint32_t hi16 = (lane >> 4) * 16;
    const uint32_t swm = (lrow & 7) << 4;
    uint32_t cswA[2][2];   // [plane][ks]
    #pragma unroll
    for (int p = 0; p < 2; p++)
        #pragma unroll
        for (int ks = 0; ks < 2; ks++)
            cswA[p][ks] = ((uint32_t)(p * 64 + ks * 32) + hi16) ^ swm;
    const uint32_t aBase = sbase + (wm + lrow) * 128;
    const uint32_t wnl = wn + lrow;
    const uint32_t q0 = wnl >> 1;
    uint32_t cswB[2];      // [ks]
    #pragma unroll
    for (int ks = 0; ks < 2; ks++)
        cswB[ks] = (((wnl & 1) * 64) + (uint32_t)(ks * 32) + hi16) ^ ((q0 & 7) << 4);
    const uint32_t bBase = sbase + B_OFF + q0 * 128;

    fill(0, 0);      cp_commit();
    fill(1, BK);     cp_commit();
    fill(2, 2 * BK); cp_commit();

    uint32_t soff = 0;
    for (int it = 0; it < KITERS; ++it) {
        if (it < KITERS - 2) cp_wait<2>();
        else if (it == KITERS - 2) cp_wait<1>();
        else cp_wait<0>();
        __syncthreads();                     // publish fill(it); stage (it+3)%4 free
        if (it + 3 < KITERS) {
            fill((it + 3) % NSTAGE, (it + 3) * BK);
            cp_commit();
        }

        const uint32_t aAddr = aBase + soff;
        const uint32_t bAddr = bBase + soff;

        uint32_t a0f[2][4], a1f[2][4];       // current-ks A fragments
        uint32_t bq[2][4];                   // B double buffer
        LDSM4(bq[0], bAddr + cswB[0]);       // unit 0: ks0,n2=0

        // 8 B-units: u = ks*4 + n2
        #pragma unroll
        for (int u = 0; u < 8; u++) {
            const int ks = u >> 2, n2 = u & 3;
            if ((u & 3) == 0) {              // (re)load A for this ks half
                #pragma unroll
                for (int mi = 0; mi < 2; mi++) {
                    LDSM4(a0f[mi], aAddr + mi * 2048 + cswA[0][ks]);
                    LDSM4(a1f[mi], aAddr + mi * 2048 + cswA[1][ks]);
                }
            }
            if (u + 1 < 8) {
                const int v = u + 1;
                LDSM4(bq[v & 1], bAddr + (v & 3) * 1024 + cswB[v >> 2]);
            }
            const uint32_t* bc = bq[u & 1];
            #pragma unroll
            for (int mi = 0; mi < 2; mi++) {
                MMA(acc[mi][2*n2],   a0f[mi], bc[0], bc[2]);
                MMA(acc[mi][2*n2+1], a0f[mi], bc[1], bc[3]);
                MMA(acc[mi][2*n2],   a1f[mi], bc[0], bc[2]);
                MMA(acc[mi][2*n2+1], a1f[mi], bc[1], bc[3]);
            }
        }
        soff = (soff == (NSTAGE - 1) * STAGE_BYTES) ? 0 : soff + STAGE_BYTES;
    }

    const int quad = lane >> 2, qt = lane & 3;

    if (mode == 1) {
        // epilogue: s_row = sum_n v[n]*tanh(E + u[b,n]); per-warp rows all in one batch
        const int b_warp = (m0 + wm) >> 6;
        const float* up = g_u + (size_t)b_warp * HH + n0 + wn;
        const float* vp = vv + n0 + wn;
        float rs[4] = {0.f, 0.f, 0.f, 0.f};
        #pragma unroll
        for (int mi = 0; mi < 2; mi++)
            #pragma unroll
            for (int ni = 0; ni < 8; ni++)
                #pragma unroll
                for (int r = 0; r < 4; r++) {
                    int col = ni * 8 + qt * 2 + (r & 1);
                    float e = acc[mi][ni][r] + __ldg(up + col);
                    rs[mi * 2 + (r >> 1)] += __ldg(vp + col) * tanhf(e);
                }
        #pragma unroll
        for (int i = 0; i < 4; i++) {
            rs[i] += __shfl_xor_sync(0xffffffffu, rs[i], 1);
            rs[i] += __shfl_xor_sync(0xffffffffu, rs[i], 2);
        }
        __syncthreads();
        if (qt == 0) {
            #pragma unroll
            for (int mi = 0; mi < 2; mi++)
                #pragma unroll
                for (int hf = 0; hf < 2; hf++)
                    srow[wid >> 2][wm + mi * 16 + hf * 8 + quad] = rs[mi * 2 + hf];
        }
        __syncthreads();
        if (tid < BM)
            g_part[blockIdx.x * MROWS + m0 + tid] = srow[0][tid] + srow[1][tid];
    } else {
        // u = D + b_attn
        #pragma unroll
        for (int mi = 0; mi < 2; mi++)
            #pragma unroll
            for (int ni = 0; ni < 8; ni++)
                #pragma unroll
                for (int r = 0; r < 4; r++) {
                    int row = m0 + wm + mi * 16 + (r >> 1) * 8 + quad;
                    int col = n0 + wn + ni * 8 + qt * 2 + (r & 1);
                    g_u[(size_t)row * HH + col] = acc[mi][ni][r] + __ldg(ba + col);
                }
    }
}

// ---------------- finalize: softmax + context + parent ----------------
// grid (BB, 4): block y covers 256 h-columns
__global__ __launch_bounds__(256) void finalize(const float* __restrict__ inp,
                                                const int* __restrict__ slen,
                                                const int* __restrict__ parent,
                                                float* __restrict__ out) {
    const int b = blockIdx.x;
    const int h0 = blockIdx.y * 256;
    const int tid = threadIdx.x;
    __shared__ float ssc[WW];
    __shared__ float sattn[WW];
    const int len = slen[b];

    if (tid < WW) {
        float s = 0.f;
        #pragma unroll
        for (int t = 0; t < NT; t++) s += g_part[t * MROWS + b * WW + tid];
        ssc[tid] = s;
    }
    __syncthreads();

    float mx = -1e30f;
    #pragma unroll 8
    for (int w = 0; w < WW; w++) mx = fmaxf(mx, ssc[w]);
    float sum = 0.f;
    #pragma unroll 8
    for (int w = 0; w < WW; w++) sum += expf(ssc[w] - mx);
    float inv = 1.f / sum;

    if (tid < WW) {
        float a = expf(ssc[tid] - mx) * inv;
        if (blockIdx.y == 0) out[b * WW + tid] = a;
        sattn[tid] = a;
    }
    __syncthreads();

    const float* base = inp + (size_t)b * SS * HH;
    const int off0 = (len - WW) * HH;
    {
        int h = h0 + tid;
        float acc = 0.f;
        #pragma unroll 8
        for (int w = 0; w < WW; w++)
            acc = fmaf(sattn[w], base[off0 + w * HH + h], acc);
        out[MROWS + b * HH + h] = acc;
        const int poff = (len - parent[b] - 1) * HH;
        out[MROWS + BB * HH + b * HH + h] = base[poff + h];
    }
}

// ---------------------------------------------------------------------------
extern "C" void kernel_launch(void* const* d_in, const int* in_sizes, int n_in,
                              void* d_out, int out_size) {
    const float* inp    = (const float*)d_in[0];
    const float* hc     = (const float*)d_in[1];
    const float* Wa     = (const float*)d_in[2];
    const float* ba     = (const float*)d_in[3];
    const float* v      = (const float*)d_in[4];
    const int*   slen   = (const int*)d_in[5];
    const int*   parent = (const int*)d_in[6];
    float* out = (float*)d_out;

    static int configured = 0;
    if (!configured) {
        cudaFuncSetAttribute(gemm_hmma, cudaFuncAttributeMaxDynamicSharedMemorySize, SMEM_ALLOC);
        configured = 1;
    }

    convert_w<<<(HH * 2 * HH) / 1024, 256>>>(Wa);
    gather_split_a<<<AROWS, 256>>>(inp, hc, slen);
    gemm_hmma<<<dim3(NT, BB / BM), 256, SMEM_ALLOC>>>(0, MROWS, 0, v, ba);   // u
    gemm_hmma<<<dim3(NT, MROWS / BM), 256, SMEM_ALLOC>>>(1, 0, HH, v, ba);   // scores
    finalize<<<dim3(BB, 4), 256>>>(inp, slen, parent, out);
}

// round 11
// speedup vs baseline: 2.2203x; 1.0956x over previous
#include <cuda_runtime.h>
#include <cuda_fp16.h>
#include <math.h>
#include <stdint.h>

#define BB 256
#define SS 512
#define HH 1024
#define WW 64
#define MROWS (BB*WW)        // 16384 score rows
#define AROWS (MROWS + BB)   // + 256 hc rows
#define NT 8                 // N tiles of 128
#define BM 128
#define BN 128
#define BK 64                // fp16 K per stage (two 32-elt halves)
#define KITERS (HH/BK)       // 16 (mode 1)
#define KSPL 4               // K-split for u-GEMM
// Per half: A rows [a0 32fp16 | a1 32fp16] = 128B SW128; B rows 32fp16=64B, 2/128B row.
#define A_HALF 16384
#define B_HALF 8192
#define B_OFF (2*A_HALF)               // 32768
#define STAGE_BYTES (2*A_HALF + 2*B_HALF)  // 49152
#define NSTAGE 2
#define SMEM_ALLOC (NSTAGE*STAGE_BYTES)    // 98304

// ---------------- scratch ----------------
__device__ __half g_A0[(size_t)AROWS*HH];
__device__ __half g_A1[(size_t)AROWS*HH];
__device__ __half g_Wh[(size_t)HH*2*HH];
__device__ float g_u4[(size_t)KSPL*BB*HH];
__device__ float g_u[(size_t)BB*HH];
__device__ float g_part[NT*MROWS];

// ---------------- PTX helpers (no sm_103a-gated features) ----------------
__device__ __forceinline__ uint32_t smem_u32(const void* p) {
    uint32_t a;
    asm("{ .reg .u64 t; cvta.to.shared.u64 t, %1; cvt.u32.u64 %0, t; }" : "=r"(a) : "l"(p));
    return a;
}
__device__ __forceinline__ void cpasync16(uint32_t dst, const void* src) {
    asm volatile("cp.async.cg.shared.global [%0], [%1], 16;" :: "r"(dst), "l"(src) : "memory");
}
__device__ __forceinline__ void cp_commit() { asm volatile("cp.async.commit_group;" ::: "memory"); }
template <int N> __device__ __forceinline__ void cp_wait() {
    asm volatile("cp.async.wait_group %0;" :: "n"(N) : "memory");
}
#define LDSM4(r, addr) \
    asm volatile("ldmatrix.sync.aligned.m8n8.x4.shared.b16 {%0,%1,%2,%3}, [%4];" \
        : "=r"((r)[0]),"=r"((r)[1]),"=r"((r)[2]),"=r"((r)[3]) : "r"(addr))
#define MMA(d, a, b0, b1) \
    asm volatile("mma.sync.aligned.m16n8k16.row.col.f32.f16.f16.f32 " \
        "{%0,%1,%2,%3},{%4,%5,%6,%7},{%8,%9},{%0,%1,%2,%3};" \
        : "+f"((d)[0]),"+f"((d)[1]),"+f"((d)[2]),"+f"((d)[3]) \
        : "r"((a)[0]),"r"((a)[1]),"r"((a)[2]),"r"((a)[3]),"r"(b0),"r"(b1))

// ---------------- split helpers ----------------
__device__ __forceinline__ void split2h(float x, __half& a0, __half& a1) {
    a0 = __float2half_rn(x);
    a1 = __float2half_rn(x - __half2float(a0));
}

// ---------------- kernel: convert W to single fp16 plane ----------------
__global__ __launch_bounds__(256) void convert_w(const float* __restrict__ Wa) {
    size_t base = ((size_t)blockIdx.x * 256 + threadIdx.x) * 4;
    float4 x = *reinterpret_cast<const float4*>(Wa + base);
    reinterpret_cast<__half2*>(g_Wh + base)[0] = __floats2half2_rn(x.x, x.y);
    reinterpret_cast<__half2*>(g_Wh + base)[1] = __floats2half2_rn(x.z, x.w);
}

// ---------------- kernel: gather rows + 2-way fp16 split ----------------
__global__ __launch_bounds__(256) void gather_split_a(const float* __restrict__ inp,
                                                      const float* __restrict__ hc,
                                                      const int* __restrict__ slen) {
    int row = blockIdx.x;
    const float* src;
    if (row < MROWS) {
        int b = row >> 6, w = row & 63;
        src = inp + ((size_t)b * SS + (slen[b] - WW + w)) * HH;
    } else {
        src = hc + (size_t)(row - MROWS) * HH;
    }
    int i = threadIdx.x * 4;
    float4 x = *reinterpret_cast<const float4*>(src + i);
    float v4[4] = {x.x, x.y, x.z, x.w};
    __half s0[4], s1[4];
    #pragma unroll
    for (int k = 0; k < 4; k++) split2h(v4[k], s0[k], s1[k]);
    size_t base = (size_t)row * HH + i;
    #pragma unroll
    for (int k = 0; k < 2; k++) {
        reinterpret_cast<__half2*>(g_A0 + base)[k] = __halves2half2(s0[2*k], s0[2*k+1]);
        reinterpret_cast<__half2*>(g_A1 + base)[k] = __halves2half2(s1[2*k], s1[2*k+1]);
    }
}

// ---------------- kernel: reduce u partials + bias ----------------
__global__ __launch_bounds__(256) void reduce_u(const float* __restrict__ ba) {
    int i = blockIdx.x * 1024 + threadIdx.x * 4;
    float4 s = *reinterpret_cast<const float4*>(g_u4 + i);
    #pragma unroll
    for (int z = 1; z < KSPL; z++) {
        float4 p = *reinterpret_cast<const float4*>(g_u4 + (size_t)z * BB * HH + i);
        s.x += p.x; s.y += p.y; s.z += p.z; s.w += p.w;
    }
    int col = i & (HH - 1);
    float4 b4 = *reinterpret_cast<const float4*>(ba + col);
    s.x += b4.x; s.y += b4.y; s.z += b4.z; s.w += b4.w;
    *reinterpret_cast<float4*>(g_u + i) = s;
}

// ---------------- HMMA GEMM: fp32 emulated via 2 fp16 products ----------------
// a = a0 + a1 (fp16 split); b single fp16. E = A0*B + A1*B.
// BK=64 (two 32-elt halves), 2-stage pipeline, single barrier per iter.
// mode 0: K-split partial u (blockIdx.z = kz) -> g_u4
// mode 1: full K scores -> g_part
__global__ __launch_bounds__(256, 2) void gemm_hmma(int mode, int arow_base, int kofs,
                                                    int niter,
                                                    const float* __restrict__ vv) {
    extern __shared__ __align__(1024) char smem_raw[];
    const uint32_t sbase = smem_u32(smem_raw);
    __shared__ float srow[2][BM];

    const int tid = threadIdx.x;
    const int lane = tid & 31;
    const int wid = tid >> 5;
    const int wm = (wid & 3) * 32;     // warp M offset
    const int wn = (wid >> 2) * 64;    // warp N offset
    const int n0 = blockIdx.x * BN;
    const int m0 = blockIdx.y * BM;
    const int kbase = blockIdx.z * (HH / KSPL);   // 0 for mode 1 (gridDim.z==1)

    // ---- A fill: 4 chunks/thread per half (rows fr0 + j*32) ----
    const int fp = (tid >> 2) & 1;     // plane
    const int fkc = tid & 3;           // 16B chunk within 32-elt half
    const int fr0 = tid >> 3;
    const __half* fbaseA = (fp ? g_A1 : g_A0)
        + (size_t)(arow_base + m0 + fr0) * HH + kbase + fkc * 8;
    const uint32_t fdstA = fr0 * 128 + (((tid & 7) * 16) ^ ((fr0 & 7) << 4));
    // ---- B fill: 2 chunks/thread per half (rows rb0, rb0+64) ----
    const int rb0 = tid >> 2;
    const __half* fbaseB0 = g_Wh + (size_t)(n0 + rb0) * (2 * HH) + kofs + kbase + fkc * 8;
    const __half* fbaseB1 = g_Wh + (size_t)(n0 + rb0 + 64) * (2 * HH) + kofs + kbase + fkc * 8;
    uint32_t fdstB0, fdstB1;
    {
        int q = rb0 >> 1;
        fdstB0 = B_OFF + q * 128 + ((((rb0 & 1) * 64) + fkc * 16) ^ ((q & 7) << 4));
        int r1 = rb0 + 64, q1 = r1 >> 1;
        fdstB1 = B_OFF + q1 * 128 + ((((r1 & 1) * 64) + fkc * 16) ^ ((q1 & 7) << 4));
    }

    auto fill = [&](int s, int k0) {
        uint32_t stg = sbase + s * STAGE_BYTES;
        #pragma unroll
        for (int h = 0; h < 2; h++) {
            #pragma unroll
            for (int j = 0; j < 4; j++)
                cpasync16(stg + fdstA + h * A_HALF + j * 4096,
                          fbaseA + (size_t)j * 32 * HH + k0 + h * 32);
            cpasync16(stg + fdstB0 + h * B_HALF, fbaseB0 + k0 + h * 32);
            cpasync16(stg + fdstB1 + h * B_HALF, fbaseB1 + k0 + h * 32);
        }
    };

    float acc[2][8][4] = {};
    // ---- LDSM bases + swizzled constants (per 32-elt half) ----
    const uint32_t lrow = lane & 15;
    const uint32_t hi16 = (lane >> 4) * 16;
    const uint32_t swm = (lrow & 7) << 4;
    uint32_t cswA[2][2];   // [plane][ks]
    #pragma unroll
    for (int p = 0; p < 2; p++)
        #pragma unroll
        for (int ks = 0; ks < 2; ks++)
            cswA[p][ks] = ((uint32_t)(p * 64 + ks * 32) + hi16) ^ swm;
    const uint32_t aBase = sbase + (wm + lrow) * 128;
    const uint32_t wnl = wn + lrow;
    const uint32_t q0 = wnl >> 1;
    uint32_t cswB[2];      // [ks]
    #pragma unroll
    for (int ks = 0; ks < 2; ks++)
        cswB[ks] = (((wnl & 1) * 64) + (uint32_t)(ks * 32) + hi16) ^ ((q0 & 7) << 4);
    const uint32_t bBase = sbase + B_OFF + q0 * 128;

    fill(0, 0);
    cp_commit();

    for (int it = 0; it < niter; ++it) {
        cp_wait<0>();          // fill(it) complete
        __syncthreads();       // publish fill(it); all warps done with other stage
        if (it + 1 < niter) {
            fill((it + 1) & 1, (it + 1) * BK);
            cp_commit();
        }

        const uint32_t soff = (uint32_t)(it & 1) * STAGE_BYTES;

        #pragma unroll
        for (int h = 0; h < 2; h++) {
            const uint32_t aAddr = aBase + soff + h * A_HALF;
            const uint32_t bAddr = bBase + soff + h * B_HALF;

            uint32_t a0f[2][4], a1f[2][4];
            uint32_t bq[2][4];
            LDSM4(bq[0], bAddr + cswB[0]);

            #pragma unroll
            for (int u = 0; u < 8; u++) {
                const int ks = u >> 2, n2 = u & 3;
                if ((u & 3) == 0) {
                    #pragma unroll
                    for (int mi = 0; mi < 2; mi++) {
                        LDSM4(a0f[mi], aAddr + mi * 2048 + cswA[0][ks]);
                        LDSM4(a1f[mi], aAddr + mi * 2048 + cswA[1][ks]);
                    }
                }
                if (u + 1 < 8) {
                    const int v = u + 1;
                    LDSM4(bq[v & 1], bAddr + (v & 3) * 1024 + cswB[v >> 2]);
                }
                const uint32_t* bc = bq[u & 1];
                #pragma unroll
                for (int mi = 0; mi < 2; mi++) {
                    MMA(acc[mi][2*n2],   a0f[mi], bc[0], bc[2]);
                    MMA(acc[mi][2*n2+1], a0f[mi], bc[1], bc[3]);
                    MMA(acc[mi][2*n2],   a1f[mi], bc[0], bc[2]);
                    MMA(acc[mi][2*n2+1], a1f[mi], bc[1], bc[3]);
                }
            }
        }
    }

    const int quad = lane >> 2, qt = lane & 3;

    if (mode == 1) {
        // epilogue: s_row = sum_n v[n]*tanh(E + u[b,n])
        const int b_warp = (m0 + wm) >> 6;
        const float* up = g_u + (size_t)b_warp * HH + n0 + wn;
        const float* vp = vv + n0 + wn;
        float rs[4] = {0.f, 0.f, 0.f, 0.f};
        #pragma unroll
        for (int mi = 0; mi < 2; mi++)
            #pragma unroll
            for (int ni = 0; ni < 8; ni++)
                #pragma unroll
                for (int r = 0; r < 4; r++) {
                    int col = ni * 8 + qt * 2 + (r & 1);
                    float e = acc[mi][ni][r] + __ldg(up + col);
                    rs[mi * 2 + (r >> 1)] += __ldg(vp + col) * tanhf(e);
                }
        #pragma unroll
        for (int i = 0; i < 4; i++) {
            rs[i] += __shfl_xor_sync(0xffffffffu, rs[i], 1);
            rs[i] += __shfl_xor_sync(0xffffffffu, rs[i], 2);
        }
        __syncthreads();
        if (qt == 0) {
            #pragma unroll
            for (int mi = 0; mi < 2; mi++)
                #pragma unroll
                for (int hf = 0; hf < 2; hf++)
                    srow[wid >> 2][wm + mi * 16 + hf * 8 + quad] = rs[mi * 2 + hf];
        }
        __syncthreads();
        if (tid < BM)
            g_part[blockIdx.x * MROWS + m0 + tid] = srow[0][tid] + srow[1][tid];
    } else {
        // partial u (no bias; reduce_u adds it)
        float* uo = g_u4 + (size_t)blockIdx.z * BB * HH;
        #pragma unroll
        for (int mi = 0; mi < 2; mi++)
            #pragma unroll
            for (int ni = 0; ni < 8; ni++)
                #pragma unroll
                for (int r = 0; r < 4; r++) {
                    int row = m0 + wm + mi * 16 + (r >> 1) * 8 + quad;
                    int col = n0 + wn + ni * 8 + qt * 2 + (r & 1);
                    uo[(size_t)row * HH + col] = acc[mi][ni][r];
                }
    }
}

// ---------------- finalize: softmax + context + parent ----------------
// grid (BB, 4): block y covers 256 h-columns
__global__ __launch_bounds__(256) void finalize(const float* __restrict__ inp,
                                                const int* __restrict__ slen,
                                                const int* __restrict__ parent,
                                                float* __restrict__ out) {
    const int b = blockIdx.x;
    const int h0 = blockIdx.y * 256;
    const int tid = threadIdx.x;
    __shared__ float ssc[WW];
    __shared__ float sattn[WW];
    const int len = slen[b];

    if (tid < WW) {
        float s = 0.f;
        #pragma unroll
        for (int t = 0; t < NT; t++) s += g_part[t * MROWS + b * WW + tid];
        ssc[tid] = s;
    }
    __syncthreads();

    float mx = -1e30f;
    #pragma unroll 8
    for (int w = 0; w < WW; w++) mx = fmaxf(mx, ssc[w]);
    float sum = 0.f;
    #pragma unroll 8
    for (int w = 0; w < WW; w++) sum += expf(ssc[w] - mx);
    float inv = 1.f / sum;

    if (tid < WW) {
        float a = expf(ssc[tid] - mx) * inv;
        if (blockIdx.y == 0) out[b * WW + tid] = a;
        sattn[tid] = a;
    }
    __syncthreads();

    const float* base = inp + (size_t)b * SS * HH;
    const int off0 = (len - WW) * HH;
    {
        int h = h0 + tid;
        float acc = 0.f;
        #pragma unroll 8
        for (int w = 0; w < WW; w++)
            acc = fmaf(sattn[w], base[off0 + w * HH + h], acc);
        out[MROWS + b * HH + h] = acc;
        const int poff = (len - parent[b] - 1) * HH;
        out[MROWS + BB * HH + b * HH + h] = base[poff + h];
    }
}

// ---------------------------------------------------------------------------
extern "C" void kernel_launch(void* const* d_in, const int* in_sizes, int n_in,
                              void* d_out, int out_size) {
    const float* inp    = (const float*)d_in[0];
    const float* hc     = (const float*)d_in[1];
    const float* Wa     = (const float*)d_in[2];
    const float* ba     = (const float*)d_in[3];
    const float* v      = (const float*)d_in[4];
    const int*   slen   = (const int*)d_in[5];
    const int*   parent = (const int*)d_in[6];
    float* out = (float*)d_out;

    static int configured = 0;
    if (!configured) {
        cudaFuncSetAttribute(gemm_hmma, cudaFuncAttributeMaxDynamicSharedMemorySize, SMEM_ALLOC);
        configured = 1;
    }

    convert_w<<<(HH * 2 * HH) / 1024, 256>>>(Wa);
    gather_split_a<<<AROWS, 256>>>(inp, hc, slen);
    // u partials: K-split x4, 4 iters each
    gemm_hmma<<<dim3(NT, BB / BM, KSPL), 256, SMEM_ALLOC>>>(0, MROWS, 0, KITERS / KSPL, v);
    reduce_u<<<(BB * HH) / 1024, 256>>>(ba);
    // scores: full K
    gemm_hmma<<<dim3(NT, MROWS / BM, 1), 256, SMEM_ALLOC>>>(1, 0, HH, KITERS, v);
    finalize<<<dim3(BB, 4), 256>>>(inp, slen, parent, out);
}